// round 9
// baseline (speedup 1.0000x reference)
#include <cuda_runtime.h>

// CoupledClustersLossV2 — persistent single-wave, 3-stage cp.async, HBM-bound.
// embeddings: [256 cls][2 pos/neg][32 samples][2048] fp32 = 128 MB.
// ||x - a||^2 = ||x||^2 - (x·s)/16 + ||s||^2/1024,  s = sum of 32 pos rows.
//
// R7 lesson: DRAM stuck at 41% because every chunk serialized on
// wait_group -> bar -> reads -> bar -> compute -> refill. Here each thread
// cp.asyncs EXACTLY the SMEM slots it later reads, so tile visibility needs
// NO barrier (self-visibility via wait_group) and stage reuse has NO
// cross-thread hazard (a thread refills only its own consumed slots).
// One barrier per chunk remains (column-sum exchange). 3 stages keep two
// 32KB chunk-groups in flight per CTA at all times, including during the
// per-item flush. Grid = 296 CTAs = exactly 2/SM, one wave.

#define NCLS     256
#define NS       32
#define DIM      2048
#define NPART    8
#define CHUNK    128
#define GRID     296
#define THREADS  256
#define NITEMS   (NCLS * NPART)               // 2048
#define ITEMS_LO (NITEMS / GRID)              // 6
#define ITEMS_REM (NITEMS - ITEMS_LO * GRID)  // 272
#define NSTAGE   3
#define TILE_F4  2048                         // 64 rows x 32 float4 = 32KB
#define SPART_F  (8 * CHUNK)                  // one colsum buffer
#define SMEM_BYTES (NSTAGE * TILE_F4 * 16 + 2 * SPART_F * 4)   // 106496
#define ROW_F4   (DIM / 4)                    // 512
#define MARGIN   0.3f

// per-(class,part) row partials: 0=||pos||^2 1=pos·s 2=||neg||^2 3=neg·s
__device__ float        g_scratch[NCLS][NPART][4][NS];
__device__ unsigned int g_done[NCLS];     // epoch counters (never reset)
__device__ float        g_class_loss[NCLS];
__device__ unsigned int g_cls_done;       // epoch counter (never reset)

__device__ __forceinline__ float dot4(float4 a, float4 b) {
    return fmaf(a.x, b.x, fmaf(a.y, b.y, fmaf(a.z, b.z, a.w * b.w)));
}
__device__ __forceinline__ float wsum(float v) {
#pragma unroll
    for (int o = 16; o > 0; o >>= 1) v += __shfl_xor_sync(0xffffffffu, v, o);
    return v;
}
__device__ __forceinline__ void cp_async16(unsigned smem_dst, const float4* gsrc) {
    asm volatile("cp.async.cg.shared.global [%0], [%1], 16;\n"
                 :: "r"(smem_dst), "l"(gsrc));
}

__global__ __launch_bounds__(THREADS, 2)
void ccl_kernel(const float* __restrict__ emb, float* __restrict__ out)
{
    extern __shared__ float4 sh4[];                       // [NSTAGE][TILE_F4]
    float* spart = (float*)(sh4 + NSTAGE * TILE_F4);      // [2][8][CHUNK]

    const int bid  = blockIdx.x;
    const int tid  = threadIdx.x;
    const int warp = tid >> 5;
    const int lane = tid & 31;

    const int n_items = (bid < ITEMS_REM) ? (ITEMS_LO + 1) : ITEMS_LO;
    const int nchunks = n_items * 2;                      // 2 halves per item

    // This thread's fixed tile slots: pos rows warp+8i, neg rows 32+warp+8i,
    // f4-col lane. SMEM byte offsets within a stage:
    const unsigned slot0  = (unsigned)((warp * 32 + lane) * 16);  // row stride 8 rows = 4096B
    const unsigned smbase = (unsigned)__cvta_generic_to_shared(sh4);

    // Issue one chunk (8 cp.async of 16B into this thread's own slots) + commit.
    auto issue = [&](int c) {
        const int item = bid + (c >> 1) * GRID;
        const int half = c & 1;
        const int cls  = item >> 3;                       // NPART == 8
        const int part = item & 7;
        const float4* g = (const float4*)emb + ((size_t)cls << 15)  // 2*NS*DIM/4
                          + (part << 6) + (half << 5)
                          + (size_t)warp * ROW_F4 + lane;
        const unsigned sb = smbase + (unsigned)(c % NSTAGE) * (TILE_F4 * 16);
#pragma unroll
        for (int i = 0; i < 4; ++i)
            cp_async16(sb + slot0 + i * 4096u, g + (size_t)(i * 8) * ROW_F4);
#pragma unroll
        for (int i = 0; i < 4; ++i)
            cp_async16(sb + 16384u + slot0 + i * 4096u,
                       g + (size_t)(NS + i * 8) * ROW_F4);
        asm volatile("cp.async.commit_group;\n" ::);
    };

    // Prologue: fill all three stages.
    issue(0); issue(1); if (nchunks > 2) issue(2);

    float pn[4], tp[4], nn[4], tn[4];

    for (int c = 0; c < nchunks; ++c) {
        const int sb = c & 1;                             // spart buffer
        const float4* tile = sh4 + (c % NSTAGE) * TILE_F4;

        // Wait for chunk c's group (self-visibility: we read our own copies).
        if (c + 2 < nchunks)      asm volatile("cp.async.wait_group 2;\n" ::);
        else if (c + 1 < nchunks) asm volatile("cp.async.wait_group 1;\n" ::);
        else                      asm volatile("cp.async.wait_group 0;\n" ::);

        // Read this thread's 4 pos + 4 neg rows (no barrier needed).
        float4 p[4], n[4];
#pragma unroll
        for (int i = 0; i < 4; ++i) {
            p[i] = tile[(warp + i * 8) * 32 + lane];
            n[i] = tile[(32 + warp + i * 8) * 32 + lane];
        }

        if ((c & 1) == 0) {                               // item start
#pragma unroll
            for (int i = 0; i < 4; ++i) { pn[i] = tp[i] = nn[i] = tn[i] = 0.f; }
        }

        // Norms (consumes p/n -> LDS done before refill below) + colsum partial.
#pragma unroll
        for (int i = 0; i < 4; ++i) {
            pn[i] += dot4(p[i], p[i]);
            nn[i] += dot4(n[i], n[i]);
        }
        float4 spv;
        spv.x = (p[0].x + p[1].x) + (p[2].x + p[3].x);
        spv.y = (p[0].y + p[1].y) + (p[2].y + p[3].y);
        spv.z = (p[0].z + p[1].z) + (p[2].z + p[3].z);
        spv.w = (p[0].w + p[1].w) + (p[2].w + p[3].w);
        *(float4*)&spart[(sb * 8 + warp) * CHUNK + lane * 4] = spv;

        __syncthreads();   // the ONLY per-chunk barrier (colsum exchange)

        // Refill this stage with chunk c+3 (our own slots, already consumed).
        if (c + 3 < nchunks) issue(c + 3);

        // Full column sums for this thread's 4 columns, then dots.
        float4 sc = *(const float4*)&spart[(sb * 8 + 0) * CHUNK + lane * 4];
#pragma unroll
        for (int w = 1; w < 8; ++w) {
            float4 t = *(const float4*)&spart[(sb * 8 + w) * CHUNK + lane * 4];
            sc.x += t.x; sc.y += t.y; sc.z += t.z; sc.w += t.w;
        }
#pragma unroll
        for (int i = 0; i < 4; ++i) {
            tp[i] += dot4(p[i], sc);
            tn[i] += dot4(n[i], sc);
        }

        if ((c & 1) == 1) {
            // ---- item flush (2 chunk-groups still in flight) ----
            const int item = bid + (c >> 1) * GRID;
            const int cls  = item >> 3;
            const int part = item & 7;
#pragma unroll
            for (int i = 0; i < 4; ++i) {
                const float a = wsum(pn[i]);
                const float b = wsum(tp[i]);
                const float d = wsum(nn[i]);
                const float e = wsum(tn[i]);
                if (lane == 0) {
                    const int row = warp + i * 8;
                    g_scratch[cls][part][0][row] = a;
                    g_scratch[cls][part][1][row] = b;
                    g_scratch[cls][part][2][row] = d;
                    g_scratch[cls][part][3][row] = e;
                }
            }
            if (lane == 0) __threadfence();
            __syncthreads();       // scratch rows visible before the count

            unsigned fin = 0;
            if (tid == 0) {
                const unsigned old = atomicAdd(&g_done[cls], 1u);
                fin = ((old & (NPART - 1u)) == (NPART - 1u)) ? 1u : 0u;
            }
            if (warp == 0) {
                fin = __shfl_sync(0xffffffffu, fin, 0);
                if (fin) {
                    // ---- per-class finisher (warp 0 only) ----
                    __threadfence();
                    float fpn = 0.f, ftp = 0.f, fnn = 0.f, ftn = 0.f;
#pragma unroll
                    for (int pp = 0; pp < NPART; ++pp) {   // fixed order
                        fpn += __ldcg(&g_scratch[cls][pp][0][lane]);
                        ftp += __ldcg(&g_scratch[cls][pp][1][lane]);
                        fnn += __ldcg(&g_scratch[cls][pp][2][lane]);
                        ftn += __ldcg(&g_scratch[cls][pp][3][lane]);
                    }
                    const float ssum  = wsum(ftp);              // ||s||^2
                    const float anorm = ssum * (1.0f / 1024.0f);
                    const float ap2   = fpn - ftp * (1.0f / 16.0f) + anorm;
                    const float nd2   = fnn - ftn * (1.0f / 16.0f) + anorm;

                    float mn = nd2;
#pragma unroll
                    for (int o = 16; o > 0; o >>= 1)
                        mn = fminf(mn, __shfl_xor_sync(0xffffffffu, mn, o));
                    const float an = sqrtf(fmaxf(mn, 0.f));

                    float t = fmaxf(sqrtf(fmaxf(ap2, 0.f)) - an + MARGIN, 0.f);
                    const float term = wsum(t * t);

                    unsigned old2 = 0;
                    if (lane == 0) {
                        g_class_loss[cls] = term;
                        __threadfence();
                        old2 = atomicAdd(&g_cls_done, 1u);
                    }
                    old2 = __shfl_sync(0xffffffffu, old2, 0);
                    if ((old2 & (NCLS - 1u)) == (NCLS - 1u)) {
                        // ---- global finisher: fixed-order mean ----
                        __threadfence();
                        float v = 0.f;
#pragma unroll
                        for (int q = 0; q < NCLS / 32; ++q)
                            v += __ldcg(&g_class_loss[q * 32 + lane]);
                        v = wsum(v);
                        if (lane == 0) out[0] = v * (1.0f / (float)NCLS);
                    }
                }
            }
        }
    }
}

extern "C" void kernel_launch(void* const* d_in, const int* in_sizes, int n_in,
                              void* d_out, int out_size)
{
    (void)in_sizes; (void)n_in; (void)out_size;
    const float* emb = (const float*)d_in[0];   // [16384, 2048] fp32
    // d_in[1] (target) is unused by the reference computation.
    cudaFuncSetAttribute(ccl_kernel, cudaFuncAttributeMaxDynamicSharedMemorySize,
                         SMEM_BYTES);
    ccl_kernel<<<GRID, THREADS, SMEM_BYTES>>>(emb, (float*)d_out);
}

// round 10
// speedup vs baseline: 1.5467x; 1.5467x over previous
#include <cuda_runtime.h>

// CoupledClustersLossV2 — one CTA per class, single wave, flush-free mainloop.
// embeddings: [256 cls][2 pos/neg][32 samples][2048] fp32 = 128 MB.
// ||x - a||^2 = ||x||^2 - (x·s)/16 + ||s||^2/1024,  s = sum of 32 pos rows.
//
// R5-R9 lesson (two-term fit over measured rounds): the streaming chunk loop
// already runs at t_c ~ 0.66us vs 0.58us DRAM floor; the per-item flush
// (16 serial shuffle chains + threadfence.gpu + global atomic) costs ~1.85us
// per item and dominated. So: NPART=1 -> 256 items total, ONE flush per CTA,
// no cross-CTA combine (no scratch, no fence/atomic per item). Mainloop keeps
// the proven R8 machinery: each thread cp.asyncs exactly the SMEM slots it
// later reads (self-visibility, no tile barrier), 3 stages, one barrier per
// chunk (column-sum exchange), fully unrolled 16-chunk loop.
// Global mean fused via epoch counter (replay-safe).

#define NCLS     256
#define NS       32
#define DIM      2048
#define CHUNK    128
#define THREADS  256
#define NCHUNKS  16                           // DIM / CHUNK, compile-time
#define NSTAGE   3
#define TILE_F4  2048                         // 64 rows x 32 float4 = 32KB
#define SPART_F  (8 * CHUNK)
#define SMEM_BYTES (NSTAGE * TILE_F4 * 16 + 2 * SPART_F * 4)   // 106496
#define ROW_F4   (DIM / 4)                    // 512
#define MARGIN   0.3f

__device__ float        g_class_loss[NCLS];
__device__ unsigned int g_cls_done;           // epoch counter (never reset)

__device__ __forceinline__ float dot4(float4 a, float4 b) {
    return fmaf(a.x, b.x, fmaf(a.y, b.y, fmaf(a.z, b.z, a.w * b.w)));
}
__device__ __forceinline__ float wsum(float v) {
#pragma unroll
    for (int o = 16; o > 0; o >>= 1) v += __shfl_xor_sync(0xffffffffu, v, o);
    return v;
}
__device__ __forceinline__ void cp_async16(unsigned smem_dst, const float4* gsrc) {
    asm volatile("cp.async.cg.shared.global [%0], [%1], 16;\n"
                 :: "r"(smem_dst), "l"(gsrc));
}

__global__ __launch_bounds__(THREADS, 2)
void ccl_kernel(const float* __restrict__ emb, float* __restrict__ out)
{
    extern __shared__ float4 sh4[];                       // [NSTAGE][TILE_F4]
    float* spart = (float*)(sh4 + NSTAGE * TILE_F4);      // [2][8][CHUNK]
    __shared__ float red[4][NS];                          // flush staging

    const int cls  = blockIdx.x;
    const int tid  = threadIdx.x;
    const int warp = tid >> 5;
    const int lane = tid & 31;

    // This thread's fixed slots: pos rows warp+8i, neg rows 32+warp+8i, f4-col lane.
    const unsigned slot0  = (unsigned)((warp * 32 + lane) * 16);
    const unsigned smbase = (unsigned)__cvta_generic_to_shared(sh4);
    const float4*  gbase  = (const float4*)emb + ((size_t)cls << 15)   // 2*NS*DIM/4
                            + (size_t)warp * ROW_F4 + lane;

    // Issue chunk c (this thread's own 8 slots) + commit.
    auto issue = [&](int c) {
        const float4*  g  = gbase + (c << 5);             // c * CHUNK/4
        const unsigned sb = smbase + (unsigned)(c % NSTAGE) * (TILE_F4 * 16);
#pragma unroll
        for (int i = 0; i < 4; ++i)
            cp_async16(sb + slot0 + i * 4096u, g + (size_t)(i * 8) * ROW_F4);
#pragma unroll
        for (int i = 0; i < 4; ++i)
            cp_async16(sb + 16384u + slot0 + i * 4096u,
                       g + (size_t)(NS + i * 8) * ROW_F4);
        asm volatile("cp.async.commit_group;\n" ::);
    };

    issue(0); issue(1); issue(2);

    float pn[4] = {0.f,0.f,0.f,0.f};
    float tp[4] = {0.f,0.f,0.f,0.f};
    float nn[4] = {0.f,0.f,0.f,0.f};
    float tn[4] = {0.f,0.f,0.f,0.f};

#pragma unroll
    for (int c = 0; c < NCHUNKS; ++c) {
        const int sb = c & 1;
        const float4* tile = sh4 + (c % NSTAGE) * TILE_F4;

        // Self-visibility: we read only our own copies -> no barrier needed.
        if (c + 2 < NCHUNKS)      asm volatile("cp.async.wait_group 2;\n" ::);
        else if (c + 1 < NCHUNKS) asm volatile("cp.async.wait_group 1;\n" ::);
        else                      asm volatile("cp.async.wait_group 0;\n" ::);

        float4 p[4], n[4];
#pragma unroll
        for (int i = 0; i < 4; ++i) {
            p[i] = tile[(warp + i * 8) * 32 + lane];
            n[i] = tile[(32 + warp + i * 8) * 32 + lane];
        }

        // Norms + per-warp column-sum partial (consumes p/n from registers).
#pragma unroll
        for (int i = 0; i < 4; ++i) {
            pn[i] += dot4(p[i], p[i]);
            nn[i] += dot4(n[i], n[i]);
        }
        float4 spv;
        spv.x = (p[0].x + p[1].x) + (p[2].x + p[3].x);
        spv.y = (p[0].y + p[1].y) + (p[2].y + p[3].y);
        spv.z = (p[0].z + p[1].z) + (p[2].z + p[3].z);
        spv.w = (p[0].w + p[1].w) + (p[2].w + p[3].w);
        *(float4*)&spart[(sb * 8 + warp) * CHUNK + lane * 4] = spv;

        __syncthreads();   // the ONLY per-chunk barrier (colsum exchange)

        // Refill this stage (our own already-consumed slots).
        if (c + 3 < NCHUNKS) issue(c + 3);

        float4 sc = *(const float4*)&spart[(sb * 8 + 0) * CHUNK + lane * 4];
#pragma unroll
        for (int w = 1; w < 8; ++w) {
            float4 t = *(const float4*)&spart[(sb * 8 + w) * CHUNK + lane * 4];
            sc.x += t.x; sc.y += t.y; sc.z += t.z; sc.w += t.w;
        }
#pragma unroll
        for (int i = 0; i < 4; ++i) {
            tp[i] += dot4(p[i], sc);
            tn[i] += dot4(n[i], sc);
        }
        // spart[sb] reused at chunk c+2, after barrier c+1 -> safe.
    }

    // ---- single end-of-CTA flush: class loss computed entirely in-CTA ----
#pragma unroll
    for (int i = 0; i < 4; ++i) {
        const float a = wsum(pn[i]);
        const float b = wsum(tp[i]);
        const float d = wsum(nn[i]);
        const float e = wsum(tn[i]);
        if (lane == 0) {
            const int row = warp + i * 8;
            red[0][row] = a;
            red[1][row] = b;
            red[2][row] = d;
            red[3][row] = e;
        }
    }
    __syncthreads();

    if (warp == 0) {
        const float pnv = red[0][lane];
        const float tpv = red[1][lane];
        const float nnv = red[2][lane];
        const float tnv = red[3][lane];

        const float ssum  = wsum(tpv);                 // ||s||^2
        const float anorm = ssum * (1.0f / 1024.0f);   // ||s||^2 / 32^2
        const float ap2   = pnv - tpv * (1.0f / 16.0f) + anorm;
        const float nd2   = nnv - tnv * (1.0f / 16.0f) + anorm;

        float mn = nd2;
#pragma unroll
        for (int o = 16; o > 0; o >>= 1)
            mn = fminf(mn, __shfl_xor_sync(0xffffffffu, mn, o));
        const float an = sqrtf(fmaxf(mn, 0.f));

        float t = fmaxf(sqrtf(fmaxf(ap2, 0.f)) - an + MARGIN, 0.f);
        const float term = wsum(t * t);

        unsigned old = 0;
        if (lane == 0) {
            g_class_loss[cls] = term;
            __threadfence();
            old = atomicAdd(&g_cls_done, 1u);
        }
        old = __shfl_sync(0xffffffffu, old, 0);
        if ((old & (NCLS - 1u)) == (NCLS - 1u)) {
            // ---- global finisher: fixed-order mean over 256 class losses ----
            __threadfence();
            float v = 0.f;
#pragma unroll
            for (int q = 0; q < NCLS / 32; ++q)
                v += __ldcg(&g_class_loss[q * 32 + lane]);
            v = wsum(v);
            if (lane == 0) out[0] = v * (1.0f / (float)NCLS);
        }
    }
}

extern "C" void kernel_launch(void* const* d_in, const int* in_sizes, int n_in,
                              void* d_out, int out_size)
{
    (void)in_sizes; (void)n_in; (void)out_size;
    const float* emb = (const float*)d_in[0];   // [16384, 2048] fp32
    // d_in[1] (target) is unused by the reference computation.
    cudaFuncSetAttribute(ccl_kernel, cudaFuncAttributeMaxDynamicSharedMemorySize,
                         SMEM_BYTES);
    ccl_kernel<<<NCLS, THREADS, SMEM_BYTES>>>(emb, (float*)d_out);
}